// round 4
// baseline (speedup 1.0000x reference)
#include <cuda_runtime.h>
#include <cuda_bf16.h>
#include <mma.h>

using namespace nvcuda;

#define N_EMBD        256
#define N_INPUTS      66
#define N_LEVELS      8
#define AND_PER_LEVEL 4096
#define NOT_PER_LEVEL 2048
#define LEVEL_N       (AND_PER_LEVEL + NOT_PER_LEVEL)
#define N_HIDDEN      1024
#define N_HID_LAYERS  8
#define LN_EPS        1e-5f

// ---------------------------------------------------------------------------
// Scratch: static device globals (no runtime allocation allowed).
// Kernels reference these directly; host never queries symbol addresses.
// ---------------------------------------------------------------------------
__device__ __align__(256) __nv_bfloat16 g_win_hi [512 * 1024];
__device__ __align__(256) __nv_bfloat16 g_win_lo [512 * 1024];
__device__ __align__(256) __nv_bfloat16 g_whid_hi[(size_t)8 * 1024 * 1024];
__device__ __align__(256) __nv_bfloat16 g_whid_lo[(size_t)8 * 1024 * 1024];
__device__ __align__(256) __nv_bfloat16 g_wout_hi[1024 * 256];
__device__ __align__(256) __nv_bfloat16 g_wout_lo[1024 * 256];
__device__ __align__(256) __nv_bfloat16 g_act0_hi[(size_t)4096 * 1024];
__device__ __align__(256) __nv_bfloat16 g_act0_lo[(size_t)4096 * 1024];
__device__ __align__(256) __nv_bfloat16 g_act1_hi[(size_t)4096 * 1024];
__device__ __align__(256) __nv_bfloat16 g_act1_lo[(size_t)4096 * 1024];
__device__ __align__(256) float         g_f32buf [(size_t)4096 * 256];

// ---------------------------------------------------------------------------
__device__ __forceinline__ void split2(float v, __nv_bfloat16& hi, __nv_bfloat16& lo) {
    hi = __float2bfloat16(v);
    lo = __float2bfloat16(v - __bfloat162float(hi));
}

// ---------------------------------------------------------------------------
// Elementwise kernels
// ---------------------------------------------------------------------------
// dst_sel: 0 -> W_in buffers, 1 -> W_hid buffers, 2 -> W_out buffers
__global__ void split_kernel(const float* __restrict__ src, int dst_sel, int n) {
    int i = blockIdx.x * blockDim.x + threadIdx.x;
    if (i >= n) return;
    __nv_bfloat16 h, l;
    split2(src[i], h, l);
    __nv_bfloat16 *hi, *lo;
    if (dst_sel == 0)      { hi = g_win_hi;  lo = g_win_lo;  }
    else if (dst_sel == 1) { hi = g_whid_hi; lo = g_whid_lo; }
    else                   { hi = g_wout_hi; lo = g_wout_lo; }
    hi[i] = h; lo[i] = l;
}

__global__ void init_kernel(const float* __restrict__ embd, float* __restrict__ out) {
    int i = blockIdx.x * blockDim.x + threadIdx.x;
    if (i < N_INPUTS * N_EMBD) out[i] = embd[i];
}

__global__ void not_kernel(float* __restrict__ node, const int* __restrict__ xe, int s) {
    int i = blockIdx.x * blockDim.x + threadIdx.x;
    if (i >= NOT_PER_LEVEL * N_EMBD) return;
    int r = i >> 8, c = i & 255;
    int src = xe[s + AND_PER_LEVEL + r];
    node[(size_t)(s + AND_PER_LEVEL + r) * N_EMBD + c] = -node[(size_t)src * N_EMBD + c];
}

// Build h = [embd[xa], embd[ya]] (4096 x 512) into act0 hi/lo (row stride 512).
__global__ void gather_kernel(const float* __restrict__ node,
                              const int* __restrict__ xe, const int* __restrict__ ye,
                              int s) {
    int i = blockIdx.x * blockDim.x + threadIdx.x;
    if (i >= AND_PER_LEVEL * 512) return;
    int m = i >> 9, c = i & 511;
    int src = (c < 256) ? xe[s + m] : ye[s + m];
    float v = node[(size_t)src * N_EMBD + (c & 255)];
    __nv_bfloat16 h, l;
    split2(v, h, l);
    g_act0_hi[i] = h; g_act0_lo[i] = l;
}

// LayerNorm per row (warp/row) of g_f32buf + b_out, write out rows [s, s+4096)
__global__ void ln_kernel(const float* __restrict__ bout,
                          const float* __restrict__ g, const float* __restrict__ b,
                          float* __restrict__ out, int s) {
    int warp = (blockIdx.x * blockDim.x + threadIdx.x) >> 5;
    int lane = threadIdx.x & 31;
    if (warp >= AND_PER_LEVEL) return;
    const float* row = g_f32buf + (size_t)warp * N_EMBD;
    float vals[8];
    float sum = 0.f, sq = 0.f;
#pragma unroll
    for (int j = 0; j < 8; j++) {
        int c = lane + j * 32;
        float v = row[c] + bout[c];
        vals[j] = v; sum += v; sq += v * v;
    }
#pragma unroll
    for (int o = 16; o > 0; o >>= 1) {
        sum += __shfl_xor_sync(0xFFFFFFFFu, sum, o);
        sq  += __shfl_xor_sync(0xFFFFFFFFu, sq,  o);
    }
    float mu  = sum * (1.0f / N_EMBD);
    float var = sq * (1.0f / N_EMBD) - mu * mu;
    float inv = rsqrtf(var + LN_EPS);
    float* orow = out + (size_t)(s + warp) * N_EMBD;
#pragma unroll
    for (int j = 0; j < 8; j++) {
        int c = lane + j * 32;
        orow[c] = (vals[j] - mu) * inv * g[c] + b[c];
    }
}

// ---------------------------------------------------------------------------
// Split-bf16 GEMM: C(f32) = (Ahi+Alo) @ (Bhi+Blo), dropping lo*lo.
// Block tile 128x128x16, 8 warps (2x4), warp tile 64x32, wmma m16n16k16 bf16.
// A row-major [4096,K] from act buffers; B row-major [K,N] from weight buffers.
// fuse=1: epilogue computes relu(x+bias) and writes bf16 hi/lo to out act pair.
// fuse=0: stores raw f32 accumulators to g_f32buf (row stride N).
// ---------------------------------------------------------------------------
#define BM 128
#define BN 128
#define BKK 16
#define A_LD (BKK + 8)          // 24
#define B_LD (BN + 8)           // 136
#define SA_ELEMS (2 * 2 * BM * A_LD)   // 12288 bf16
#define SB_ELEMS (2 * 2 * BKK * B_LD)  // 8704 bf16
#define SMEM_BYTES ((SA_ELEMS + SB_ELEMS) * 2)  // 41984 bytes

__device__ __forceinline__ __nv_bfloat16* sA_at(__nv_bfloat16* base, int st, int hl, int r, int c) {
    return base + (((st * 2 + hl) * BM + r) * A_LD + c);
}
__device__ __forceinline__ __nv_bfloat16* sB_at(__nv_bfloat16* base, int st, int hl, int r, int c) {
    return base + (SA_ELEMS + ((st * 2 + hl) * BKK + r) * B_LD + c);
}

__global__ __launch_bounds__(256) void gemm_split(
    int K, int N, int a_sel, int b_sel, int layer, int out_sel, int fuse,
    const float* __restrict__ bias) {
    extern __shared__ char smem_raw[];
    __nv_bfloat16* sm = (__nv_bfloat16*)smem_raw;

    const __nv_bfloat16* Ahi = a_sel ? g_act1_hi : g_act0_hi;
    const __nv_bfloat16* Alo = a_sel ? g_act1_lo : g_act0_lo;
    const __nv_bfloat16 *Bhi, *Blo;
    if (b_sel == 0)      { Bhi = g_win_hi;  Blo = g_win_lo; }
    else if (b_sel == 1) {
        Bhi = g_whid_hi + (size_t)layer * N_HIDDEN * N_HIDDEN;
        Blo = g_whid_lo + (size_t)layer * N_HIDDEN * N_HIDDEN;
    } else               { Bhi = g_wout_hi; Blo = g_wout_lo; }

    const int tid    = threadIdx.x;
    const int warpId = tid >> 5;
    const int lane   = tid & 31;
    const int wm     = warpId >> 2;   // 0..1
    const int wn     = warpId & 3;    // 0..3
    const int rowBase = blockIdx.y * BM;
    const int colBase = blockIdx.x * BN;

    const int a_row = tid >> 1;
    const int a_col = (tid & 1) * 8;
    const int b_row = tid >> 4;
    const int b_col = (tid & 15) * 8;

    const __nv_bfloat16* Ahi_p = Ahi + (size_t)(rowBase + a_row) * K + a_col;
    const __nv_bfloat16* Alo_p = Alo + (size_t)(rowBase + a_row) * K + a_col;
    const __nv_bfloat16* Bhi_p = Bhi + (size_t)b_row * N + colBase + b_col;
    const __nv_bfloat16* Blo_p = Blo + (size_t)b_row * N + colBase + b_col;

    wmma::fragment<wmma::accumulator, 16, 16, 16, float> acc[4][2];
#pragma unroll
    for (int m = 0; m < 4; m++)
#pragma unroll
        for (int n = 0; n < 2; n++)
            wmma::fill_fragment(acc[m][n], 0.0f);

    const int kTiles = K / BKK;

    // prologue: stage 0
    {
        int4 rah = *(const int4*)(Ahi_p);
        int4 ral = *(const int4*)(Alo_p);
        int4 rbh = *(const int4*)(Bhi_p);
        int4 rbl = *(const int4*)(Blo_p);
        *(int4*)sA_at(sm, 0, 0, a_row, a_col) = rah;
        *(int4*)sA_at(sm, 0, 1, a_row, a_col) = ral;
        *(int4*)sB_at(sm, 0, 0, b_row, b_col) = rbh;
        *(int4*)sB_at(sm, 0, 1, b_row, b_col) = rbl;
    }
    __syncthreads();

    for (int kt = 0; kt < kTiles; ++kt) {
        const int  cur     = kt & 1;
        const int  nxt     = cur ^ 1;
        const bool hasNext = (kt + 1) < kTiles;

        int4 rah, ral, rbh, rbl;
        if (hasNext) {
            const int koff = (kt + 1) * BKK;
            rah = *(const int4*)(Ahi_p + koff);
            ral = *(const int4*)(Alo_p + koff);
            rbh = *(const int4*)(Bhi_p + (size_t)koff * N);
            rbl = *(const int4*)(Blo_p + (size_t)koff * N);
        }

        wmma::fragment<wmma::matrix_a, 16, 16, 16, __nv_bfloat16, wmma::row_major> fa_hi[4], fa_lo[4];
        wmma::fragment<wmma::matrix_b, 16, 16, 16, __nv_bfloat16, wmma::row_major> fb_hi[2], fb_lo[2];
#pragma unroll
        for (int m = 0; m < 4; m++) {
            wmma::load_matrix_sync(fa_hi[m], sA_at(sm, cur, 0, wm * 64 + m * 16, 0), A_LD);
            wmma::load_matrix_sync(fa_lo[m], sA_at(sm, cur, 1, wm * 64 + m * 16, 0), A_LD);
        }
#pragma unroll
        for (int n = 0; n < 2; n++) {
            wmma::load_matrix_sync(fb_hi[n], sB_at(sm, cur, 0, 0, wn * 32 + n * 16), B_LD);
            wmma::load_matrix_sync(fb_lo[n], sB_at(sm, cur, 1, 0, wn * 32 + n * 16), B_LD);
        }

#pragma unroll
        for (int m = 0; m < 4; m++)
#pragma unroll
            for (int n = 0; n < 2; n++)
                wmma::mma_sync(acc[m][n], fa_hi[m], fb_hi[n], acc[m][n]);
#pragma unroll
        for (int m = 0; m < 4; m++)
#pragma unroll
            for (int n = 0; n < 2; n++)
                wmma::mma_sync(acc[m][n], fa_hi[m], fb_lo[n], acc[m][n]);
#pragma unroll
        for (int m = 0; m < 4; m++)
#pragma unroll
            for (int n = 0; n < 2; n++)
                wmma::mma_sync(acc[m][n], fa_lo[m], fb_hi[n], acc[m][n]);

        if (hasNext) {
            *(int4*)sA_at(sm, nxt, 0, a_row, a_col) = rah;
            *(int4*)sA_at(sm, nxt, 1, a_row, a_col) = ral;
            *(int4*)sB_at(sm, nxt, 0, b_row, b_col) = rbh;
            *(int4*)sB_at(sm, nxt, 1, b_row, b_col) = rbl;
        }
        __syncthreads();
    }

    if (fuse) {
        // Fused bias + relu + bf16 split. Reuse smem as per-warp f32 staging:
        // each warp owns 64x16 floats (4 KB). Two column-halves sequentially.
        __nv_bfloat16* Ohi = out_sel ? g_act1_hi : g_act0_hi;
        __nv_bfloat16* Olo = out_sel ? g_act1_lo : g_act0_lo;
        float* epiw = (float*)smem_raw + warpId * 1024;
#pragma unroll
        for (int n = 0; n < 2; n++) {
#pragma unroll
            for (int m = 0; m < 4; m++)
                wmma::store_matrix_sync(epiw + m * 256, acc[m][n], 16, wmma::mem_row_major);
            __syncwarp();
            const int gc = colBase + wn * 32 + n * 16;
#pragma unroll
            for (int ii = 0; ii < 32; ii++) {
                int i = lane + ii * 32;
                int r = i >> 4, c = i & 15;
                float v = epiw[i] + bias[gc + c];
                v = fmaxf(v, 0.0f);
                __nv_bfloat16 h, l;
                split2(v, h, l);
                size_t gi = (size_t)(rowBase + wm * 64 + r) * N + gc + c;
                Ohi[gi] = h; Olo[gi] = l;
            }
            __syncwarp();
        }
    } else {
#pragma unroll
        for (int m = 0; m < 4; m++)
#pragma unroll
            for (int n = 0; n < 2; n++) {
                float* cp = g_f32buf + (size_t)(rowBase + wm * 64 + m * 16) * N
                            + colBase + wn * 32 + n * 16;
                wmma::store_matrix_sync(cp, acc[m][n], N, wmma::mem_row_major);
            }
    }
}

// ---------------------------------------------------------------------------
// Launch: pure kernel launches, graph-capturable, no allocation, no sync.
// ---------------------------------------------------------------------------
extern "C" void kernel_launch(void* const* d_in, const int* in_sizes, int n_in,
                              void* d_out, int out_size) {
    (void)in_sizes; (void)n_in; (void)out_size;

    const int*   xe         = (const int*)d_in[1];
    const int*   ye         = (const int*)d_in[2];
    const float* input_embd = (const float*)d_in[3];
    const float* W_in       = (const float*)d_in[4];
    const float* b_in       = (const float*)d_in[5];
    const float* W_hid      = (const float*)d_in[6];
    const float* b_hid      = (const float*)d_in[7];
    const float* W_out      = (const float*)d_in[8];
    const float* b_out      = (const float*)d_in[9];
    const float* ln_g       = (const float*)d_in[10];
    const float* ln_b       = (const float*)d_in[11];
    float*       out        = (float*)d_out;

    // Split weights to bf16 hi/lo
    split_kernel<<<(512 * 1024 + 255) / 256, 256>>>(W_in, 0, 512 * 1024);
    split_kernel<<<(8 * 1024 * 1024 + 255) / 256, 256>>>(W_hid, 1, 8 * 1024 * 1024);
    split_kernel<<<(1024 * 256 + 255) / 256, 256>>>(W_out, 2, 1024 * 256);

    init_kernel<<<(N_INPUTS * N_EMBD + 255) / 256, 256>>>(input_embd, out);

    const dim3 gridH(N_HIDDEN / BN, AND_PER_LEVEL / BM);   // (8, 32)
    const dim3 gridO(N_EMBD / BN, AND_PER_LEVEL / BM);     // (2, 32)

    for (int l = 0; l < N_LEVELS; l++) {
        const int s = N_INPUTS + l * LEVEL_N;

        not_kernel<<<(NOT_PER_LEVEL * N_EMBD + 255) / 256, 256>>>(out, xe, s);
        gather_kernel<<<(AND_PER_LEVEL * 512 + 255) / 256, 256>>>(out, xe, ye, s);

        // input layer: act0 (4096x512) @ W_in (512x1024) -> act1 (fused relu)
        gemm_split<<<gridH, 256, SMEM_BYTES>>>(512, N_HIDDEN,
                                               /*a_sel=*/0, /*b_sel=*/0, 0,
                                               /*out_sel=*/1, /*fuse=*/1, b_in);

        // hidden layers: ping-pong act1 <-> act0
        for (int i = 0; i < N_HID_LAYERS; i++) {
            int a_sel   = (i & 1) ? 0 : 1;
            int o_sel   = 1 - a_sel;
            gemm_split<<<gridH, 256, SMEM_BYTES>>>(N_HIDDEN, N_HIDDEN,
                                                   a_sel, /*b_sel=*/1, i,
                                                   o_sel, /*fuse=*/1,
                                                   b_hid + (size_t)i * N_HIDDEN);
        }

        // output layer: act1 (4096x1024) @ W_out (1024x256) -> g_f32buf (raw f32)
        gemm_split<<<gridO, 256, SMEM_BYTES>>>(N_HIDDEN, N_EMBD,
                                               /*a_sel=*/1, /*b_sel=*/2, 0,
                                               /*out_sel=*/0, /*fuse=*/0, b_out);

        // bias + layernorm -> node_embd rows [s, s+4096)
        ln_kernel<<<(AND_PER_LEVEL * 32 + 255) / 256, 256>>>(b_out, ln_g, ln_b, out, s);
    }
}

// round 8
// speedup vs baseline: 1.2678x; 1.2678x over previous
#include <cuda_runtime.h>
#include <cuda_bf16.h>
#include <mma.h>
#include <cstdint>

using namespace nvcuda;

#define N_EMBD        256
#define N_INPUTS      66
#define N_LEVELS      8
#define AND_PER_LEVEL 4096
#define NOT_PER_LEVEL 2048
#define LEVEL_N       (AND_PER_LEVEL + NOT_PER_LEVEL)
#define N_HIDDEN      1024
#define N_HID_LAYERS  8
#define LN_EPS        1e-5f

// ---------------------------------------------------------------------------
// Scratch: static device globals. Weights kept [K, N] row-major (as given).
// ---------------------------------------------------------------------------
__device__ __align__(256) __nv_bfloat16 g_win_hi [(size_t)512 * 1024];
__device__ __align__(256) __nv_bfloat16 g_win_lo [(size_t)512 * 1024];
__device__ __align__(256) __nv_bfloat16 g_whid_hi[(size_t)8 * 1024 * 1024];
__device__ __align__(256) __nv_bfloat16 g_whid_lo[(size_t)8 * 1024 * 1024];
__device__ __align__(256) __nv_bfloat16 g_wout_hi[(size_t)1024 * 256];
__device__ __align__(256) __nv_bfloat16 g_wout_lo[(size_t)1024 * 256];
__device__ __align__(256) __nv_bfloat16 g_act0_hi[(size_t)4096 * 1024];
__device__ __align__(256) __nv_bfloat16 g_act0_lo[(size_t)4096 * 1024];
__device__ __align__(256) __nv_bfloat16 g_act1_hi[(size_t)4096 * 1024];
__device__ __align__(256) __nv_bfloat16 g_act1_lo[(size_t)4096 * 1024];

// ---------------------------------------------------------------------------
__device__ __forceinline__ void split2(float v, __nv_bfloat16& hi, __nv_bfloat16& lo) {
    hi = __float2bfloat16(v);
    lo = __float2bfloat16(v - __bfloat162float(hi));
}

__device__ __forceinline__ uint32_t smem_u32(const void* p) {
    uint32_t a;
    asm("{ .reg .u64 t; cvta.to.shared.u64 t, %1; cvt.u32.u64 %0, t; }" : "=r"(a) : "l"(p));
    return a;
}

#define CP_ASYNC16(dst, src) \
    asm volatile("cp.async.cg.shared.global [%0], [%1], 16;" :: "r"(dst), "l"(src) : "memory")
#define CP_COMMIT() asm volatile("cp.async.commit_group;" ::: "memory")
#define CP_WAIT1()  asm volatile("cp.async.wait_group 1;" ::: "memory")
#define CP_WAIT0()  asm volatile("cp.async.wait_group 0;" ::: "memory")

// ---------------------------------------------------------------------------
// Elementwise kernels
// ---------------------------------------------------------------------------
// dst_sel: 0 -> W_in, 1 -> W_hid, 2 -> W_out
__global__ void split_kernel(const float* __restrict__ src, int dst_sel, int n) {
    int i = blockIdx.x * blockDim.x + threadIdx.x;
    if (i >= n) return;
    __nv_bfloat16 h, l;
    split2(src[i], h, l);
    __nv_bfloat16 *hi, *lo;
    if (dst_sel == 0)      { hi = g_win_hi;  lo = g_win_lo;  }
    else if (dst_sel == 1) { hi = g_whid_hi; lo = g_whid_lo; }
    else                   { hi = g_wout_hi; lo = g_wout_lo; }
    hi[i] = h; lo[i] = l;
}

__global__ void init_kernel(const float* __restrict__ embd, float* __restrict__ out) {
    int i = blockIdx.x * blockDim.x + threadIdx.x;
    if (i < N_INPUTS * N_EMBD) out[i] = embd[i];
}

__global__ void not_kernel(float* __restrict__ node, const int* __restrict__ xe, int s) {
    int i = blockIdx.x * blockDim.x + threadIdx.x;
    if (i >= NOT_PER_LEVEL * N_EMBD) return;
    int r = i >> 8, c = i & 255;
    int src = xe[s + AND_PER_LEVEL + r];
    node[(size_t)(s + AND_PER_LEVEL + r) * N_EMBD + c] = -node[(size_t)src * N_EMBD + c];
}

// Build h = [embd[xa], embd[ya]] (4096 x 512) into act0 hi/lo (row stride 512).
__global__ void gather_kernel(const float* __restrict__ node,
                              const int* __restrict__ xe, const int* __restrict__ ye, int s) {
    int i = blockIdx.x * blockDim.x + threadIdx.x;
    if (i >= AND_PER_LEVEL * 512) return;
    int m = i >> 9, c = i & 511;
    int src = (c < 256) ? xe[s + m] : ye[s + m];
    float v = node[(size_t)src * N_EMBD + (c & 255)];
    __nv_bfloat16 h, l; split2(v, h, l);
    g_act0_hi[i] = h; g_act0_lo[i] = l;
}

// ---------------------------------------------------------------------------
// Split-bf16 pipelined GEMM.
// C = (Ahi+Alo) @ (Bhi+Blo) dropping lo*lo. Block tile BM x 256, K-chunk 32.
// 8 warps as 2x4; warp tile (BM/2) x 64; wmma m16n16k16 bf16.
// 3-stage cp.async smem pipeline.
// fuse=1: relu(x+bias) -> bf16 hi/lo into act[out_sel] (row stride Nout).
// fuse=2: bias + LayerNorm over full 256-col rows -> f32 outp rows [s+rowBase..].
// ---------------------------------------------------------------------------
#define A_LD 40
#define B_LD 264

template<int BM>
__global__ __launch_bounds__(256, 1) void gemm_pipe(
    int K, int Nout, int a_sel, int b_sel, int layer, int out_sel, int fuse,
    const float* __restrict__ bias, float* __restrict__ outp, int s,
    const float* __restrict__ ln_g, const float* __restrict__ ln_b) {

    constexpr int WM  = BM / 2;            // warp tile M
    constexpr int MF  = WM / 16;           // m-fragments per warp
    constexpr uint32_t ASB = 2u * BM * A_LD * 2u;   // A hi+lo stage bytes
    constexpr uint32_t BSB = 2u * 32 * B_LD * 2u;   // B hi+lo stage bytes
    constexpr uint32_t SS  = ASB + BSB;             // stage size

    extern __shared__ __align__(128) char dsm[];

    const int tid = threadIdx.x, warpId = tid >> 5, lane = tid & 31;
    const int wm = warpId >> 2, wn = warpId & 3;
    const int rowBase = blockIdx.y * BM;
    const int colBase = blockIdx.x * 256;

    const __nv_bfloat16* Ahi = a_sel ? g_act1_hi : g_act0_hi;
    const __nv_bfloat16* Alo = a_sel ? g_act1_lo : g_act0_lo;
    const __nv_bfloat16 *Bhi, *Blo;
    if (b_sel == 0)      { Bhi = g_win_hi;  Blo = g_win_lo; }
    else if (b_sel == 1) { Bhi = g_whid_hi + (size_t)layer * N_HIDDEN * N_HIDDEN;
                           Blo = g_whid_lo + (size_t)layer * N_HIDDEN * N_HIDDEN; }
    else                 { Bhi = g_wout_hi; Blo = g_wout_lo; }

    const uint32_t sbase0 = smem_u32(dsm);

    wmma::fragment<wmma::accumulator, 16, 16, 16, float> acc[MF][4];
#pragma unroll
    for (int m = 0; m < MF; m++)
#pragma unroll
        for (int n = 0; n < 4; n++)
            wmma::fill_fragment(acc[m][n], 0.0f);

    const int NK = K >> 5;   // 32-K chunks

    auto load_stage = [&](int stg, int k0) {
        const uint32_t sb = sbase0 + (uint32_t)stg * SS;
        // A hi/lo: BM x 32 bf16 -> BM*4 16B vectors each
#pragma unroll
        for (int h = 0; h < 2; h++) {
            const __nv_bfloat16* ap = h ? Alo : Ahi;
            const uint32_t so = sb + h * (BM * A_LD * 2u);
#pragma unroll
            for (int i = 0; i < BM / 64; i++) {
                int v = tid + i * 256;
                int r = v >> 2, cv = v & 3;
                CP_ASYNC16(so + (uint32_t)(r * A_LD + cv * 8) * 2u,
                           ap + (size_t)(rowBase + r) * K + k0 + cv * 8);
            }
        }
        // B hi/lo: 32 x 256 bf16 -> 1024 16B vectors each
#pragma unroll
        for (int h = 0; h < 2; h++) {
            const __nv_bfloat16* bp = h ? Blo : Bhi;
            const uint32_t so = sb + ASB + h * (32 * B_LD * 2u);
#pragma unroll
            for (int i = 0; i < 4; i++) {
                int v = tid + i * 256;
                int r = v >> 5, cv = v & 31;
                CP_ASYNC16(so + (uint32_t)(r * B_LD + cv * 8) * 2u,
                           bp + (size_t)(k0 + r) * Nout + colBase + cv * 8);
            }
        }
        CP_COMMIT();
    };

    // prologue: stages 0, 1
    load_stage(0, 0);
    load_stage(1, 32);

    for (int kt = 0; kt < NK; kt++) {
        if (kt + 1 < NK) CP_WAIT1(); else CP_WAIT0();
        __syncthreads();
        if (kt + 2 < NK) load_stage((kt + 2) % 3, (kt + 2) * 32);

        const int stg = kt % 3;
        __nv_bfloat16* sA   = (__nv_bfloat16*)(dsm + (size_t)stg * SS);
        __nv_bfloat16* sAlo = sA + BM * A_LD;
        __nv_bfloat16* sB   = (__nv_bfloat16*)(dsm + (size_t)stg * SS + ASB);
        __nv_bfloat16* sBlo = sB + 32 * B_LD;

#pragma unroll
        for (int ks = 0; ks < 32; ks += 16) {
            wmma::fragment<wmma::matrix_a, 16, 16, 16, __nv_bfloat16, wmma::row_major> fah[MF], fal[MF];
            wmma::fragment<wmma::matrix_b, 16, 16, 16, __nv_bfloat16, wmma::row_major> fbh[4], fbl[4];
#pragma unroll
            for (int m = 0; m < MF; m++)
                wmma::load_matrix_sync(fah[m], sA + (wm * WM + m * 16) * A_LD + ks, A_LD);
#pragma unroll
            for (int n = 0; n < 4; n++)
                wmma::load_matrix_sync(fbh[n], sB + ks * B_LD + wn * 64 + n * 16, B_LD);
#pragma unroll
            for (int m = 0; m < MF; m++)
#pragma unroll
                for (int n = 0; n < 4; n++)
                    wmma::mma_sync(acc[m][n], fah[m], fbh[n], acc[m][n]);
#pragma unroll
            for (int n = 0; n < 4; n++)
                wmma::load_matrix_sync(fbl[n], sBlo + ks * B_LD + wn * 64 + n * 16, B_LD);
#pragma unroll
            for (int m = 0; m < MF; m++)
#pragma unroll
                for (int n = 0; n < 4; n++)
                    wmma::mma_sync(acc[m][n], fah[m], fbl[n], acc[m][n]);
#pragma unroll
            for (int m = 0; m < MF; m++)
                wmma::load_matrix_sync(fal[m], sAlo + (wm * WM + m * 16) * A_LD + ks, A_LD);
#pragma unroll
            for (int m = 0; m < MF; m++)
#pragma unroll
                for (int n = 0; n < 4; n++)
                    wmma::mma_sync(acc[m][n], fal[m], fbh[n], acc[m][n]);
        }
    }

    __syncthreads();   // pipeline smem reads done; safe to reuse smem below

    if (fuse == 1) {
        __nv_bfloat16* Ohi = out_sel ? g_act1_hi : g_act0_hi;
        __nv_bfloat16* Olo = out_sel ? g_act1_lo : g_act0_lo;
        float* epiw = (float*)dsm + warpId * (WM * 16);
#pragma unroll
        for (int n = 0; n < 4; n++) {
#pragma unroll
            for (int m = 0; m < MF; m++)
                wmma::store_matrix_sync(epiw + m * 256, acc[m][n], 16, wmma::mem_row_major);
            __syncwarp();
            const int gc0 = colBase + wn * 64 + n * 16;
#pragma unroll
            for (int ii = 0; ii < WM / 2; ii++) {
                int i = lane + ii * 32;
                int r = i >> 4, c = i & 15;
                float v = fmaxf(epiw[i] + __ldg(bias + gc0 + c), 0.0f);
                __nv_bfloat16 h, l; split2(v, h, l);
                size_t gi = (size_t)(rowBase + wm * WM + r) * Nout + gc0 + c;
                Ohi[gi] = h; Olo[gi] = l;
            }
            __syncwarp();
        }
    } else {
        // fuse == 2: bias + LayerNorm (Nout == 256, colBase == 0)
        float* cbuf = (float*)dsm;                       // [BM][260]
#pragma unroll
        for (int m = 0; m < MF; m++)
#pragma unroll
            for (int n = 0; n < 4; n++)
                wmma::store_matrix_sync(cbuf + (wm * WM + m * 16) * 260 + wn * 64 + n * 16,
                                        acc[m][n], 260, wmma::mem_row_major);
        __syncthreads();
        const int rpw = BM / 8;
        for (int j = 0; j < rpw; j++) {
            int r = warpId * rpw + j;
            const float* row = cbuf + r * 260;
            float vals[8];
            float sum = 0.f, sq = 0.f;
#pragma unroll
            for (int k = 0; k < 8; k++) {
                int c = lane + k * 32;
                float v = row[c] + __ldg(bias + c);
                vals[k] = v; sum += v; sq += v * v;
            }
#pragma unroll
            for (int o = 16; o > 0; o >>= 1) {
                sum += __shfl_xor_sync(0xFFFFFFFFu, sum, o);
                sq  += __shfl_xor_sync(0xFFFFFFFFu, sq,  o);
            }
            float mu  = sum * (1.0f / N_EMBD);
            float var = sq * (1.0f / N_EMBD) - mu * mu;
            float inv = rsqrtf(var + LN_EPS);
            float* orow = outp + (size_t)(s + rowBase + r) * N_EMBD;
#pragma unroll
            for (int k = 0; k < 8; k++) {
                int c = lane + k * 32;
                orow[c] = (vals[k] - mu) * inv * __ldg(ln_g + c) + __ldg(ln_b + c);
            }
        }
    }
}

// ---------------------------------------------------------------------------
// Launch: kernel launches only; graph-capturable; no allocation; no sync.
// ---------------------------------------------------------------------------
extern "C" void kernel_launch(void* const* d_in, const int* in_sizes, int n_in,
                              void* d_out, int out_size) {
    (void)in_sizes; (void)n_in; (void)out_size;

    const int*   xe         = (const int*)d_in[1];
    const int*   ye         = (const int*)d_in[2];
    const float* input_embd = (const float*)d_in[3];
    const float* W_in       = (const float*)d_in[4];
    const float* b_in       = (const float*)d_in[5];
    const float* W_hid      = (const float*)d_in[6];
    const float* b_hid      = (const float*)d_in[7];
    const float* W_out      = (const float*)d_in[8];
    const float* b_out      = (const float*)d_in[9];
    const float* ln_g       = (const float*)d_in[10];
    const float* ln_b       = (const float*)d_in[11];
    float*       out        = (float*)d_out;

    // Stage sizes (bytes): must match device constexprs
    const uint32_t SS128 = (2u * 128 * A_LD * 2u) + (2u * 32 * B_LD * 2u);  // 54272
    const uint32_t SS64  = (2u * 64  * A_LD * 2u) + (2u * 32 * B_LD * 2u);  // 44032
    cudaFuncSetAttribute(gemm_pipe<128>, cudaFuncAttributeMaxDynamicSharedMemorySize, 3 * SS128);
    cudaFuncSetAttribute(gemm_pipe<64>,  cudaFuncAttributeMaxDynamicSharedMemorySize, 3 * SS64);

    // Split weights to bf16 hi/lo
    split_kernel<<<(512 * 1024 + 255) / 256, 256>>>(W_in, 0, 512 * 1024);
    split_kernel<<<(8 * 1024 * 1024 + 255) / 256, 256>>>(W_hid, 1, 8 * 1024 * 1024);
    split_kernel<<<(1024 * 256 + 255) / 256, 256>>>(W_out, 2, 1024 * 256);

    init_kernel<<<(N_INPUTS * N_EMBD + 255) / 256, 256>>>(input_embd, out);

    const dim3 gridH(N_HIDDEN / 256, AND_PER_LEVEL / 128);  // (4, 32) = 128 CTAs
    const dim3 gridO(1, AND_PER_LEVEL / 64);                // (1, 64) = 64 CTAs

    for (int l = 0; l < N_LEVELS; l++) {
        const int s = N_INPUTS + l * LEVEL_N;

        not_kernel<<<(NOT_PER_LEVEL * N_EMBD + 255) / 256, 256>>>(out, xe, s);
        gather_kernel<<<(AND_PER_LEVEL * 512 + 255) / 256, 256>>>(out, xe, ye, s);

        // input layer: act0 (4096x512) @ W_in (512x1024) -> act1 (relu, split)
        gemm_pipe<128><<<gridH, 256, 3 * SS128>>>(512, N_HIDDEN, 0, 0, 0, 1, 1,
                                                  b_in, nullptr, 0, nullptr, nullptr);

        // hidden layers: ping-pong act1 <-> act0
        for (int i = 0; i < N_HID_LAYERS; i++) {
            int a_sel = (i & 1) ? 0 : 1;
            int o_sel = 1 - a_sel;
            gemm_pipe<128><<<gridH, 256, 3 * SS128>>>(N_HIDDEN, N_HIDDEN, a_sel, 1, i, o_sel, 1,
                                                      b_hid + (size_t)i * N_HIDDEN,
                                                      nullptr, 0, nullptr, nullptr);
        }

        // output layer: act1 (4096x1024) @ W_out (1024x256) -> bias+LN -> out
        gemm_pipe<64><<<gridO, 256, 3 * SS64>>>(N_HIDDEN, N_EMBD, 1, 2, 0, 0, 2,
                                                b_out, out, s, ln_g, ln_b);
    }
}